// round 7
// baseline (speedup 1.0000x reference)
#include <cuda_runtime.h>

// Two Euler steps of a Gaussian-RBF point flow — SINGLE persistent kernel.
//   Phase A: dp1 for all 16384 rows (32 rows/CTA, 512 CTAs); builds pair-packed
//            pass-2 source tables + shape1.
//   Grid barrier (monotonic counter; all 512 CTAs are wave-1 resident at occ 4).
//   Phase B: dp2 partials; CTA pair (2k,2k+1) covers one 32-row target group,
//            each CTA half of the j-range. Second CTA to finish (monotonic
//            parity flag) combines partials and writes the output.
// Inner exponent is the safe combined form arg = u*x + v*y + a + cri <= 0.
// FFMA2 packs pairs of source points; lane = output row; smem tables
// pre-paired -> LDS.128 broadcasts.

#define NSRC  2048
#define NTGT  2048
#define NLAND 4096
#define NB    4
#define NPAIR 1024
#define NCTA  512
#define TAUF  0.5f
#define LOG2E 1.4426950408889634f

typedef unsigned long long ull;

// Cross-phase scratch (device globals; no allocation).
__device__ float4 g_pk_uv[NB * NPAIR];   // (u0,u1,v0,v1)   from shape1 source pts
__device__ float4 g_pk_ap[NB * NPAIR];   // (a0,a1,px0,px1)
__device__ float2 g_pk_py[NB * NPAIR];   // (py0,py1)
__device__ float2 g_s1t[NB * NTGT];      // shape1 of target rows
__device__ float2 g_p2[2][NB * NTGT];    // phase-B partial dp per j-half
__device__ ull      g_ctr;               // grid barrier, monotonic across calls
__device__ unsigned g_flag[NB * NTGT / 32];  // 256 group flags, monotonic parity

__device__ __forceinline__ float ex2f(float x) {
    float y;
    asm("ex2.approx.ftz.f32 %0, %1;" : "=f"(y) : "f"(x));
    return y;
}
__device__ __forceinline__ ull fma2(ull a, ull b, ull c) {
    ull d;
    asm("fma.rn.f32x2 %0, %1, %2, %3;" : "=l"(d) : "l"(a), "l"(b), "l"(c));
    return d;
}
__device__ __forceinline__ ull add2(ull a, ull b) {
    ull d;
    asm("add.rn.f32x2 %0, %1, %2;" : "=l"(d) : "l"(a), "l"(b));
    return d;
}
__device__ __forceinline__ ull pack2(float lo, float hi) {
    ull d;
    asm("mov.b64 %0, {%1, %2};" : "=l"(d) : "f"(lo), "f"(hi));
    return d;
}
__device__ __forceinline__ void unpack2(ull v, float& lo, float& hi) {
    asm("mov.b64 {%0, %1}, %2;" : "=f"(lo), "=f"(hi) : "l"(v));
}

// One packed step: Gaussians for source points (2q, 2q+1) vs this lane's row.
__device__ __forceinline__ void rbf_pair(
    const float4* __restrict__ sUV, const float4* __restrict__ sAP,
    const float2* __restrict__ sPY, int q,
    ull xp, ull yp, ull crip, ull& ax, ull& ay)
{
    ulonglong2 UV = *(const ulonglong2*)&sUV[q];   // .x=(u0,u1) .y=(v0,v1)
    ulonglong2 AP = *(const ulonglong2*)&sAP[q];   // .x=(a0,a1) .y=(px0,px1)
    ull PY = *(const ull*)&sPY[q];                 // (py0,py1)
    ull arg = add2(fma2(UV.y, yp, fma2(UV.x, xp, AP.x)), crip);
    float a0, a1;
    unpack2(arg, a0, a1);
    ull wp = pack2(ex2f(a0), ex2f(a1));
    ax = fma2(wp, AP.y, ax);
    ay = fma2(wp, PY, ay);
}

// ---------------------------------------------------------------------------
__global__ __launch_bounds__(256, 4) void fused_kernel(
    const float2* __restrict__ mom,
    const float2* __restrict__ src,
    const float2* __restrict__ tgt,
    const float*  __restrict__ sig,
    float2*       __restrict__ out)
{
    __shared__ float4 sUV[NPAIR];
    __shared__ float4 sAP[NPAIR];
    __shared__ float2 sPY[NPAIR];
    __shared__ ull sRX[8][32];
    __shared__ ull sRY[8][32];
    __shared__ unsigned sSecond;

    const int tid  = threadIdx.x;
    const int w    = tid >> 5;
    const int lane = tid & 31;

    const float c2 = -LOG2E / sig[0];
    const float m2 = -2.0f * c2;

    // ======================= Phase A: dp1 / shape1 =======================
    {
        const int i0 = blockIdx.x * 32;          // land row base (0..16383)
        const int b  = i0 >> 12;
        const int li = i0 & (NLAND - 1);

        const float2* __restrict__ srcb = src + b * NSRC;
        const float2* __restrict__ momb = mom + b * NSRC;

        for (int q = tid; q < NPAIR; q += 256) {
            float2 s0 = srcb[2 * q],     s1 = srcb[2 * q + 1];
            float2 p0 = momb[2 * q],     p1 = momb[2 * q + 1];
            sUV[q] = make_float4(m2 * s0.x, m2 * s1.x, m2 * s0.y, m2 * s1.y);
            sAP[q] = make_float4(c2 * (s0.x * s0.x + s0.y * s0.y),
                                 c2 * (s1.x * s1.x + s1.y * s1.y), p0.x, p1.x);
            sPY[q] = make_float2(p0.y, p1.y);
        }
        __syncthreads();

        const int i = li + lane;
        float2 X = (li < NSRC) ? srcb[i] : tgt[b * NTGT + i - NSRC];
        const ull xp = pack2(X.x, X.x);
        const ull yp = pack2(X.y, X.y);
        const float cri = c2 * (X.x * X.x + X.y * X.y);
        const ull crip = pack2(cri, cri);

        ull ax0 = 0ull, ay0 = 0ull, ax1 = 0ull, ay1 = 0ull;
        const int qb = w * 128;
        #pragma unroll 8
        for (int t = 0; t < 128; t += 2) {
            rbf_pair(sUV, sAP, sPY, qb + t,     xp, yp, crip, ax0, ay0);
            rbf_pair(sUV, sAP, sPY, qb + t + 1, xp, yp, crip, ax1, ay1);
        }
        sRX[w][lane] = add2(ax0, ax1);
        sRY[w][lane] = add2(ay0, ay1);
        __syncthreads();

        if (w == 0) {
            ull sx = sRX[0][lane], sy = sRY[0][lane];
            #pragma unroll
            for (int ww = 1; ww < 8; ww++) {
                sx = add2(sx, sRX[ww][lane]);
                sy = add2(sy, sRY[ww][lane]);
            }
            float e0, e1, f0, f1;
            unpack2(sx, e0, e1);
            unpack2(sy, f0, f1);
            float s1x = fmaf(TAUF, e0 + e1, X.x);
            float s1y = fmaf(TAUF, f0 + f1, X.y);

            if (li < NSRC) {
                float2 p = momb[i];
                float u = m2 * s1x, v = m2 * s1y;
                float a = c2 * (s1x * s1x + s1y * s1y);
                float uh  = __shfl_xor_sync(0xffffffffu, u,   1);
                float vh  = __shfl_xor_sync(0xffffffffu, v,   1);
                float ah  = __shfl_xor_sync(0xffffffffu, a,   1);
                float pxh = __shfl_xor_sync(0xffffffffu, p.x, 1);
                float pyh = __shfl_xor_sync(0xffffffffu, p.y, 1);
                if ((lane & 1) == 0) {
                    const int q = (b * NSRC + i) >> 1;
                    g_pk_uv[q] = make_float4(u, uh, v, vh);
                    g_pk_ap[q] = make_float4(a, ah, p.x, pxh);
                    g_pk_py[q] = make_float2(p.y, pyh);
                }
            } else {
                g_s1t[b * NTGT + i - NSRC] = make_float2(s1x, s1y);
            }
        }
    }

    // ======================= Grid barrier =======================
    // Monotonic counter: each call adds exactly NCTA; target is the end of
    // this call's contiguous block. Graph-replay-safe, no reset needed.
    __threadfence();                 // release phase-A stores (all threads)
    __syncthreads();
    if (tid == 0) {
        ull old = atomicAdd(&g_ctr, 1ull);
        ull target = (old & ~(ull)(NCTA - 1)) + (ull)NCTA;
        while (*(volatile ull*)&g_ctr < target) __nanosleep(64);
        __threadfence();             // acquire
    }
    __syncthreads();

    // ======================= Phase B: dp2 partials =======================
    {
        const int grp = blockIdx.x >> 1;         // 0..255 target row group
        const int s   = blockIdx.x & 1;          // j-half
        const int i0  = grp * 32;                // target row base (0..8191)
        const int b   = i0 >> 11;

        const int qg = b * NPAIR + s * 512;
        for (int q = tid; q < 512; q += 256) {
            sUV[q] = g_pk_uv[qg + q];
            sAP[q] = g_pk_ap[qg + q];
            sPY[q] = g_pk_py[qg + q];
        }
        __syncthreads();

        const int i = i0 + lane;
        float2 X = g_s1t[i];
        const ull xp = pack2(X.x, X.x);
        const ull yp = pack2(X.y, X.y);
        const float cri = c2 * (X.x * X.x + X.y * X.y);
        const ull crip = pack2(cri, cri);

        ull ax0 = 0ull, ay0 = 0ull, ax1 = 0ull, ay1 = 0ull;
        const int qb = w * 64;
        #pragma unroll 8
        for (int t = 0; t < 64; t += 2) {
            rbf_pair(sUV, sAP, sPY, qb + t,     xp, yp, crip, ax0, ay0);
            rbf_pair(sUV, sAP, sPY, qb + t + 1, xp, yp, crip, ax1, ay1);
        }
        sRX[w][lane] = add2(ax0, ax1);
        sRY[w][lane] = add2(ay0, ay1);
        __syncthreads();

        if (w == 0) {
            ull sx = sRX[0][lane], sy = sRY[0][lane];
            #pragma unroll
            for (int ww = 1; ww < 8; ww++) {
                sx = add2(sx, sRX[ww][lane]);
                sy = add2(sy, sRY[ww][lane]);
            }
            float e0, e1, f0, f1;
            unpack2(sx, e0, e1);
            unpack2(sy, f0, f1);
            g_p2[s][i] = make_float2(e0 + e1, f0 + f1);
        }
        __threadfence();             // release partial (all threads)
        __syncthreads();

        // Monotonic parity flag: exactly one of the two partner CTAs sees an
        // odd prior value each call -> it performs the combine + writeout.
        if (tid == 0) {
            unsigned old = atomicAdd(&g_flag[grp], 1u);
            sSecond = old & 1u;
            __threadfence();         // acquire
        }
        __syncthreads();

        if (sSecond && w == 0) {
            float2 p0 = __ldcg(&g_p2[0][i]);
            float2 p1 = __ldcg(&g_p2[1][i]);
            out[i] = make_float2(fmaf(TAUF, p0.x + p1.x, X.x),
                                 fmaf(TAUF, p0.y + p1.y, X.y));
        }
    }
}

// ---------------------------------------------------------------------------
extern "C" void kernel_launch(void* const* d_in, const int* in_sizes, int n_in,
                              void* d_out, int out_size)
{
    const float2* mom = (const float2*)d_in[0];
    const float2* src = (const float2*)d_in[1];
    const float2* tgt = (const float2*)d_in[2];
    const float*  sig = (const float*)d_in[3];
    float2* out = (float2*)d_out;

    fused_kernel<<<NCTA, 256>>>(mom, src, tgt, sig, out);
}

// round 8
// speedup vs baseline: 1.1178x; 1.1178x over previous
#include <cuda_runtime.h>

// Two Euler steps of a Gaussian-RBF point flow — single persistent kernel,
// register row-blocking x4 to cut LDS traffic (the measured bottleneck).
//   Phase A: dp1 for all 16384 rows. 128 CTAs x 512 thr; CTA = 128 rows
//            (4 rows/lane), 16 warps split the 1024 j-pairs (64 steps each).
//            Builds pair-packed pass-2 tables + shape1.
//   Grid barrier (monotonic counter; all 128 CTAs wave-1 resident).
//   Phase B: dp2. CTA pair = one 128-row target group, each CTA half the
//            j-range (32 steps/warp); parity-flag combine writes output.
// Inner exponent: safe combined form arg = u*x + v*y + a + cri <= 0.
// FFMA2 packs PAIRS OF SOURCE POINTS; one 40B table load per j-pair now
// serves 4 rows.

#define NSRC  2048
#define NTGT  2048
#define NLAND 4096
#define NB    4
#define NPAIR 1024
#define NCTA  128
#define TAUF  0.5f
#define LOG2E 1.4426950408889634f

typedef unsigned long long ull;

// Cross-phase scratch (device globals; no allocation).
__device__ float4 g_pk_uv[NB * NPAIR];   // (u0,u1,v0,v1)  from shape1 source pts
__device__ float4 g_pk_ap[NB * NPAIR];   // (a0,a1,px0,px1)
__device__ float2 g_pk_py[NB * NPAIR];   // (py0,py1)
__device__ float2 g_s1t[NB * NTGT];      // shape1 of target rows
__device__ float2 g_p2[2][NB * NTGT];    // phase-B partial dp per j-half
__device__ ull      g_ctr;               // grid barrier, monotonic across calls
__device__ unsigned g_flag[64];          // per-group parity, monotonic

__device__ __forceinline__ float ex2f(float x) {
    float y;
    asm("ex2.approx.ftz.f32 %0, %1;" : "=f"(y) : "f"(x));
    return y;
}
__device__ __forceinline__ ull fma2(ull a, ull b, ull c) {
    ull d;
    asm("fma.rn.f32x2 %0, %1, %2, %3;" : "=l"(d) : "l"(a), "l"(b), "l"(c));
    return d;
}
__device__ __forceinline__ ull add2(ull a, ull b) {
    ull d;
    asm("add.rn.f32x2 %0, %1, %2;" : "=l"(d) : "l"(a), "l"(b));
    return d;
}
__device__ __forceinline__ ull pack2(float lo, float hi) {
    ull d;
    asm("mov.b64 %0, {%1, %2};" : "=l"(d) : "f"(lo), "f"(hi));
    return d;
}
__device__ __forceinline__ void unpack2(ull v, float& lo, float& hi) {
    asm("mov.b64 {%0, %1}, %2;" : "=f"(lo), "=f"(hi) : "l"(v));
}

// One row's packed update for a loaded j-pair.
__device__ __forceinline__ void rbf_row(
    ull UVx, ull UVy, ull APa, ull APp, ull PY,
    ull xp, ull yp, ull crip, ull& ax, ull& ay)
{
    ull arg = add2(fma2(UVy, yp, fma2(UVx, xp, APa)), crip);
    float a0, a1;
    unpack2(arg, a0, a1);
    ull wp = pack2(ex2f(a0), ex2f(a1));
    ax = fma2(wp, APp, ax);
    ay = fma2(wp, PY, ay);
}

// ---------------------------------------------------------------------------
__global__ __launch_bounds__(512, 1) void fused_kernel(
    const float2* __restrict__ mom,
    const float2* __restrict__ src,
    const float2* __restrict__ tgt,
    const float*  __restrict__ sig,
    float2*       __restrict__ out)
{
    __shared__ __align__(16) char SM[40960];

    const int tid  = threadIdx.x;
    const int w    = tid >> 5;
    const int lane = tid & 31;

    const float c2 = -LOG2E / sig[0];
    const float m2 = -2.0f * c2;

    // ======================= Phase A =======================
    {
        float4* sUV = (float4*)(SM);            // [1024] 16KB
        float4* sAP = (float4*)(SM + 16384);    // [1024] 16KB
        float2* sPY = (float2*)(SM + 32768);    // [1024] 8KB

        const int i0 = blockIdx.x * 128;        // land row base (0..16383)
        const int b  = i0 >> 12;
        const int li = i0 & (NLAND - 1);

        const float2* __restrict__ srcb = src + b * NSRC;
        const float2* __restrict__ momb = mom + b * NSRC;

        for (int q = tid; q < NPAIR; q += 512) {
            float2 s0 = srcb[2 * q], s1 = srcb[2 * q + 1];
            float2 p0 = momb[2 * q], p1 = momb[2 * q + 1];
            sUV[q] = make_float4(m2 * s0.x, m2 * s1.x, m2 * s0.y, m2 * s1.y);
            sAP[q] = make_float4(c2 * (s0.x * s0.x + s0.y * s0.y),
                                 c2 * (s1.x * s1.x + s1.y * s1.y), p0.x, p1.x);
            sPY[q] = make_float2(p0.y, p1.y);
        }
        __syncthreads();

        float2 X[4];
        ull xp[4], yp[4], crip[4];
        #pragma unroll
        for (int r = 0; r < 4; r++) {
            const int i = li + 32 * r + lane;
            X[r] = (li < NSRC) ? srcb[i] : tgt[b * NTGT + i - NSRC];
            xp[r] = pack2(X[r].x, X[r].x);
            yp[r] = pack2(X[r].y, X[r].y);
            float cri = c2 * (X[r].x * X[r].x + X[r].y * X[r].y);
            crip[r] = pack2(cri, cri);
        }

        ull ax[4] = {0,0,0,0}, ay[4] = {0,0,0,0};
        const int qb = w * 64;
        #pragma unroll 8
        for (int t = 0; t < 64; t++) {
            ulonglong2 UV = *(const ulonglong2*)&sUV[qb + t];
            ulonglong2 AP = *(const ulonglong2*)&sAP[qb + t];
            ull PY = *(const ull*)&sPY[qb + t];
            #pragma unroll
            for (int r = 0; r < 4; r++)
                rbf_row(UV.x, UV.y, AP.x, AP.y, PY,
                        xp[r], yp[r], crip[r], ax[r], ay[r]);
        }

        // Two-stage 16->8->1 warp reduction; buffer aliases the (dead) UV table.
        __syncthreads();                        // all table reads complete
        typedef ull RedRow[256];
        RedRow* red = (RedRow*)(SM);            // red[8][256] = 16KB
        ull own[8] = {ax[0], ay[0], ax[1], ay[1], ax[2], ay[2], ax[3], ay[3]};
        if (w >= 8) {
            #pragma unroll
            for (int k = 0; k < 8; k++) red[k][(w - 8) * 32 + lane] = own[k];
        }
        __syncthreads();
        if (w < 8) {
            #pragma unroll
            for (int k = 0; k < 8; k++)
                red[k][w * 32 + lane] = add2(red[k][w * 32 + lane], own[k]);
        }
        __syncthreads();

        if (w == 0) {
            ull s[8];
            #pragma unroll
            for (int k = 0; k < 8; k++) {
                ull acc = red[k][lane];
                #pragma unroll
                for (int ww = 1; ww < 8; ww++)
                    acc = add2(acc, red[k][ww * 32 + lane]);
                s[k] = acc;
            }
            #pragma unroll
            for (int r = 0; r < 4; r++) {
                float e0, e1, f0, f1;
                unpack2(s[2 * r],     e0, e1);
                unpack2(s[2 * r + 1], f0, f1);
                float s1x = fmaf(TAUF, e0 + e1, X[r].x);
                float s1y = fmaf(TAUF, f0 + f1, X[r].y);
                const int i = li + 32 * r + lane;
                if (li < NSRC) {
                    float2 p = momb[i];
                    float u = m2 * s1x, v = m2 * s1y;
                    float a = c2 * (s1x * s1x + s1y * s1y);
                    float uh  = __shfl_xor_sync(0xffffffffu, u,   1);
                    float vh  = __shfl_xor_sync(0xffffffffu, v,   1);
                    float ah  = __shfl_xor_sync(0xffffffffu, a,   1);
                    float pxh = __shfl_xor_sync(0xffffffffu, p.x, 1);
                    float pyh = __shfl_xor_sync(0xffffffffu, p.y, 1);
                    if ((lane & 1) == 0) {
                        const int q = (b * NSRC + i) >> 1;
                        g_pk_uv[q] = make_float4(u, uh, v, vh);
                        g_pk_ap[q] = make_float4(a, ah, p.x, pxh);
                        g_pk_py[q] = make_float2(p.y, pyh);
                    }
                } else {
                    g_s1t[b * NTGT + i - NSRC] = make_float2(s1x, s1y);
                }
            }
        }
    }

    // ======================= Grid barrier =======================
    __threadfence();
    __syncthreads();
    if (tid == 0) {
        ull old = atomicAdd(&g_ctr, 1ull);
        ull target = (old & ~(ull)(NCTA - 1)) + (ull)NCTA;
        while (*(volatile ull*)&g_ctr < target) __nanosleep(64);
        __threadfence();
    }
    __syncthreads();

    // ======================= Phase B =======================
    {
        float4* sUV = (float4*)(SM);            // [512] 8KB
        float4* sAP = (float4*)(SM + 8192);     // [512] 8KB
        float2* sPY = (float2*)(SM + 16384);    // [512] 4KB
        typedef ull RedRow[256];
        RedRow* red = (RedRow*)(SM + 20480);    // red[8][256] = 16KB (no alias)

        const int grp = blockIdx.x >> 1;        // 0..63 target row group
        const int sj  = blockIdx.x & 1;         // j-half
        const int i0  = grp * 128;              // target row base (0..8191)
        const int b   = i0 >> 11;

        const int qg = b * NPAIR + sj * 512;
        {
            const int q = tid;                  // 512 threads, 512 entries
            sUV[q] = g_pk_uv[qg + q];
            sAP[q] = g_pk_ap[qg + q];
            sPY[q] = g_pk_py[qg + q];
        }
        __syncthreads();

        float2 X[4];
        ull xp[4], yp[4], crip[4];
        #pragma unroll
        for (int r = 0; r < 4; r++) {
            X[r] = g_s1t[i0 + 32 * r + lane];
            xp[r] = pack2(X[r].x, X[r].x);
            yp[r] = pack2(X[r].y, X[r].y);
            float cri = c2 * (X[r].x * X[r].x + X[r].y * X[r].y);
            crip[r] = pack2(cri, cri);
        }

        ull ax[4] = {0,0,0,0}, ay[4] = {0,0,0,0};
        const int qb = w * 32;
        #pragma unroll 8
        for (int t = 0; t < 32; t++) {
            ulonglong2 UV = *(const ulonglong2*)&sUV[qb + t];
            ulonglong2 AP = *(const ulonglong2*)&sAP[qb + t];
            ull PY = *(const ull*)&sPY[qb + t];
            #pragma unroll
            for (int r = 0; r < 4; r++)
                rbf_row(UV.x, UV.y, AP.x, AP.y, PY,
                        xp[r], yp[r], crip[r], ax[r], ay[r]);
        }

        ull own[8] = {ax[0], ay[0], ax[1], ay[1], ax[2], ay[2], ax[3], ay[3]};
        if (w >= 8) {
            #pragma unroll
            for (int k = 0; k < 8; k++) red[k][(w - 8) * 32 + lane] = own[k];
        }
        __syncthreads();
        if (w < 8) {
            #pragma unroll
            for (int k = 0; k < 8; k++)
                red[k][w * 32 + lane] = add2(red[k][w * 32 + lane], own[k]);
        }
        __syncthreads();

        if (w == 0) {
            float dx[4], dy[4];
            #pragma unroll
            for (int r = 0; r < 4; r++) {
                ull sx = red[2 * r][lane], sy = red[2 * r + 1][lane];
                #pragma unroll
                for (int ww = 1; ww < 8; ww++) {
                    sx = add2(sx, red[2 * r][ww * 32 + lane]);
                    sy = add2(sy, red[2 * r + 1][ww * 32 + lane]);
                }
                float e0, e1, f0, f1;
                unpack2(sx, e0, e1);
                unpack2(sy, f0, f1);
                dx[r] = e0 + e1;
                dy[r] = f0 + f1;
                g_p2[sj][i0 + 32 * r + lane] = make_float2(dx[r], dy[r]);
            }
            __threadfence();                    // release partials (warp 0)
            __syncwarp();
            unsigned old = 0;
            if (lane == 0) old = atomicAdd(&g_flag[grp], 1u);
            old = __shfl_sync(0xffffffffu, old, 0);
            if (old & 1u) {                     // second arrival: combine
                __threadfence();                // acquire peer partials
                #pragma unroll
                for (int r = 0; r < 4; r++) {
                    const int i = i0 + 32 * r + lane;
                    float2 pp = __ldcg(&g_p2[sj ^ 1][i]);
                    out[i] = make_float2(fmaf(TAUF, dx[r] + pp.x, X[r].x),
                                         fmaf(TAUF, dy[r] + pp.y, X[r].y));
                }
            }
        }
    }
}

// ---------------------------------------------------------------------------
extern "C" void kernel_launch(void* const* d_in, const int* in_sizes, int n_in,
                              void* d_out, int out_size)
{
    const float2* mom = (const float2*)d_in[0];
    const float2* src = (const float2*)d_in[1];
    const float2* tgt = (const float2*)d_in[2];
    const float*  sig = (const float*)d_in[3];
    float2* out = (float2*)d_out;

    fused_kernel<<<NCTA, 512>>>(mom, src, tgt, sig, out);
}